// round 3
// baseline (speedup 1.0000x reference)
#include <cuda_runtime.h>
#include <math.h>

#define DQ 256
#define H1 512
#define MAXT 8
#define TILE_M 128
#define TILE_N 128
#define TILE_K 16

// ---- scratch (no allocations allowed) ----
__device__ int g_cnt[MAXT];
__device__ int g_cur[MAXT];
__device__ int g_off[MAXT + 1];
__device__ int g_perm[262144 + MAXT * TILE_M];

// ---- packed f32x2 helpers (Blackwell FFMA2 path) ----
__device__ __forceinline__ void ffma2(unsigned long long& d,
                                      unsigned long long a,
                                      unsigned long long b) {
    asm("fma.rn.f32x2 %0, %1, %2, %0;" : "+l"(d) : "l"(a), "l"(b));
}
__device__ __forceinline__ void unpack2(float& lo, float& hi, unsigned long long v) {
    asm("mov.b64 {%0, %1}, %2;" : "=f"(lo), "=f"(hi) : "l"(v));
}

// ---- 1: zero counters ----
__global__ void k_zero() {
    if (threadIdx.x < MAXT) g_cnt[threadIdx.x] = 0;
}

// ---- 2: histogram of types (block-aggregated) ----
__global__ void k_count(const int* __restrict__ Z, int n) {
    __shared__ int sc[MAXT];
    if (threadIdx.x < MAXT) sc[threadIdx.x] = 0;
    __syncthreads();
    int i = blockIdx.x * blockDim.x + threadIdx.x;
    if (i < n) atomicAdd(&sc[Z[i]], 1);
    __syncthreads();
    if (threadIdx.x < MAXT) {
        int c = sc[threadIdx.x];
        if (c) atomicAdd(&g_cnt[threadIdx.x], c);
    }
}

// ---- 3: tiny scan -> padded per-type segment offsets ----
__global__ void k_scan(int T) {
    if (threadIdx.x == 0 && blockIdx.x == 0) {
        int off = 0;
        for (int t = 0; t < T; t++) {
            g_off[t] = off;
            g_cur[t] = off;
            off += ((g_cnt[t] + TILE_M - 1) / TILE_M) * TILE_M;
        }
        for (int t = T; t <= MAXT; t++) g_off[t] = off;
    }
}

// ---- 4: scatter atom indices into grouped layout ----
__global__ void k_scatter(const int* __restrict__ Z, int n) {
    int i = blockIdx.x * blockDim.x + threadIdx.x;
    if (i < n) {
        int z = Z[i];
        int pos = atomicAdd(&g_cur[z], 1);
        g_perm[pos] = i;
    }
}

// ---- 5: fused grouped GEMM + tanh + dot(W1) + b1 ----
__global__ __launch_bounds__(256, 2) void k_gemm(
    const float* __restrict__ q, const float* __restrict__ W0,
    const float* __restrict__ b0, const float* __restrict__ W1,
    const float* __restrict__ b1, float* __restrict__ out, int T) {

    __shared__ __align__(16) float qs[TILE_K][2 * TILE_M + 8];   // duplicated pairs
    __shared__ __align__(16) float ws[TILE_K][TILE_N];
    __shared__ float red[TILE_M][17];
    __shared__ int sperm[TILE_M];
    __shared__ int sinfo[2];

    const int tid = threadIdx.x;
    const int tstart = blockIdx.x * TILE_M;

    if (tid == 0) {
        int t = 0;
        while (t < T && tstart >= g_off[t + 1]) t++;
        int nv = 0;
        if (t < T) nv = min(TILE_M, g_cnt[t] - (tstart - g_off[t]));
        sinfo[0] = t;
        sinfo[1] = nv;
    }
    __syncthreads();
    const int t = sinfo[0];
    const int nvalid = sinfo[1];
    if (nvalid <= 0) return;

    if (tid < TILE_M)
        sperm[tid] = (tid < nvalid) ? g_perm[tstart + tid] : g_perm[tstart];
    __syncthreads();

    const int tx = tid & 15;
    const int ty = tid >> 4;

    float pf[8];
#pragma unroll
    for (int i = 0; i < 8; i++) pf[i] = 0.0f;

    const float* w0base = W0 + (size_t)t * DQ * H1;

    for (int c = 0; c < H1 / TILE_N; c++) {
        unsigned long long acc[8][4];
#pragma unroll
        for (int i = 0; i < 8; i++)
#pragma unroll
            for (int j = 0; j < 4; j++) acc[i][j] = 0ull;

        for (int kb = 0; kb < DQ / TILE_K; kb++) {
#pragma unroll
            for (int l = 0; l < 2; l++) {
                int idx = tid + l * 256;
                int row = idx >> 2;
                int kq = idx & 3;
                int n = sperm[row];
                float4 v = *reinterpret_cast<const float4*>(
                    &q[(size_t)n * DQ + kb * TILE_K + kq * 4]);
                *reinterpret_cast<float2*>(&qs[kq * 4 + 0][2 * row]) = make_float2(v.x, v.x);
                *reinterpret_cast<float2*>(&qs[kq * 4 + 1][2 * row]) = make_float2(v.y, v.y);
                *reinterpret_cast<float2*>(&qs[kq * 4 + 2][2 * row]) = make_float2(v.z, v.z);
                *reinterpret_cast<float2*>(&qs[kq * 4 + 3][2 * row]) = make_float2(v.w, v.w);
            }
#pragma unroll
            for (int l = 0; l < 2; l++) {
                int idx = tid + l * 256;
                int kk = idx >> 5;
                int hq = idx & 31;
                *reinterpret_cast<float4*>(&ws[kk][hq * 4]) =
                    *reinterpret_cast<const float4*>(
                        &w0base[(size_t)(kb * TILE_K + kk) * H1 + c * TILE_N + hq * 4]);
            }
            __syncthreads();

#pragma unroll
            for (int k = 0; k < TILE_K; k++) {
                unsigned long long a2[8];
                const ulonglong2* ap =
                    reinterpret_cast<const ulonglong2*>(&qs[k][2 * (ty * 8)]);
#pragma unroll
                for (int i = 0; i < 4; i++) {
                    ulonglong2 v = ap[i];
                    a2[2 * i] = v.x;
                    a2[2 * i + 1] = v.y;
                }
                unsigned long long b2[4];
                const ulonglong2* bp =
                    reinterpret_cast<const ulonglong2*>(&ws[k][tx * 8]);
#pragma unroll
                for (int j = 0; j < 2; j++) {
                    ulonglong2 v = bp[j];
                    b2[2 * j] = v.x;
                    b2[2 * j + 1] = v.y;
                }
#pragma unroll
                for (int i = 0; i < 8; i++)
#pragma unroll
                    for (int j = 0; j < 4; j++) ffma2(acc[i][j], a2[i], b2[j]);
            }
            __syncthreads();
        }

        const int hbase = t * H1 + c * TILE_N + tx * 8;
        float b0v[8], w1v[8];
#pragma unroll
        for (int j = 0; j < 8; j++) {
            b0v[j] = __ldg(&b0[hbase + j]);
            w1v[j] = __ldg(&W1[hbase + j]);
        }
#pragma unroll
        for (int i = 0; i < 8; i++) {
#pragma unroll
            for (int j2 = 0; j2 < 4; j2++) {
                float lo, hi;
                unpack2(lo, hi, acc[i][j2]);
                float h0 = tanhf(lo + b0v[2 * j2]);
                float h1 = tanhf(hi + b0v[2 * j2 + 1]);
                pf[i] += h0 * w1v[2 * j2] + h1 * w1v[2 * j2 + 1];
            }
        }
    }

    __syncthreads();
#pragma unroll
    for (int i = 0; i < 8; i++) red[ty * 8 + i][tx] = pf[i];
    __syncthreads();

    if (tid < TILE_M && tid < nvalid) {
        float s = 0.0f;
#pragma unroll
        for (int x = 0; x < 16; x++) s += red[tid][x];
        out[sperm[tid]] = s + __ldg(&b1[0]);
    }
}

extern "C" void kernel_launch(void* const* d_in, const int* in_sizes, int n_in,
                              void* d_out, int out_size) {
    const float* q  = (const float*)d_in[0];
    const int*   Z  = (const int*)d_in[1];
    const float* W0 = (const float*)d_in[2];
    const float* b0 = (const float*)d_in[3];
    const float* W1 = (const float*)d_in[4];
    const float* b1 = (const float*)d_in[5];
    float* out = (float*)d_out;

    const int N = in_sizes[1];
    int T = in_sizes[3] / H1;
    if (T < 1) T = 1;
    if (T > MAXT) T = MAXT;

    k_zero<<<1, 32>>>();
    k_count<<<(N + 255) / 256, 256>>>(Z, N);
    k_scan<<<1, 1>>>(T);
    k_scatter<<<(N + 255) / 256, 256>>>(Z, N);

    const int tiles = (N + TILE_M - 1) / TILE_M + T;
    k_gemm<<<tiles, 256>>>(q, W0, b0, W1, b1, out, T);
}

// round 6
// speedup vs baseline: 5.5441x; 5.5441x over previous
#include <cuda_runtime.h>
#include <cuda_fp16.h>
#include <math.h>
#include <stdint.h>

#define DQ 256
#define H1 512
#define MAXT 8
#define TILE_M 128
#define LDA 264              // halves per A row (128B-conflict-free phases)
#define LDB 264
#define SP_INFO 0
#define SP_PERM 16
#define SP_B0S  544
#define SP_W1S  2592
#define SP_RED  4640
#define SP_A    6784
#define B_BUF_BYTES (32 * LDB * 2)      // 16896
#define SP_B    74368                   // SP_A + 128*LDA*2 = 6784 + 67584
#define SM_DYN  (SP_B + 2 * B_BUF_BYTES)  // 108160

// ---------------- scratch ----------------
__device__ int g_cnt[MAXT];
__device__ int g_cur[MAXT];
__device__ int g_off[MAXT + 1];
__device__ int g_perm[131072 + MAXT * TILE_M];
__device__ __align__(16) __half g_w0h[MAXT * DQ * H1];   // fp16 W0, [t][k][h]

// ---------------- asm helpers (sm_103-safe: no 'a' features) ----------------
__device__ __forceinline__ uint32_t smem_u32(const void* p) {
    uint32_t a;
    asm("{ .reg .u64 t; cvta.to.shared.u64 t, %1; cvt.u32.u64 %0, t; }" : "=r"(a) : "l"(p));
    return a;
}
__device__ __forceinline__ void ldsm_x4(uint32_t* r, uint32_t addr) {
    asm volatile("ldmatrix.sync.aligned.m8n8.x4.shared.b16 {%0,%1,%2,%3}, [%4];"
                 : "=r"(r[0]), "=r"(r[1]), "=r"(r[2]), "=r"(r[3]) : "r"(addr));
}
__device__ __forceinline__ void ldsm_x4_t(uint32_t* r, uint32_t addr) {
    asm volatile("ldmatrix.sync.aligned.m8n8.x4.trans.shared.b16 {%0,%1,%2,%3}, [%4];"
                 : "=r"(r[0]), "=r"(r[1]), "=r"(r[2]), "=r"(r[3]) : "r"(addr));
}
__device__ __forceinline__ void mma16816(float* c, const uint32_t* a, uint32_t b0, uint32_t b1) {
    asm volatile(
        "mma.sync.aligned.m16n8k16.row.col.f32.f16.f16.f32 "
        "{%0,%1,%2,%3}, {%4,%5,%6,%7}, {%8,%9}, {%0,%1,%2,%3};"
        : "+f"(c[0]), "+f"(c[1]), "+f"(c[2]), "+f"(c[3])
        : "r"(a[0]), "r"(a[1]), "r"(a[2]), "r"(a[3]), "r"(b0), "r"(b1));
}
__device__ __forceinline__ void cp16(uint32_t dst, const void* src) {
    asm volatile("cp.async.cg.shared.global [%0], [%1], 16;" :: "r"(dst), "l"(src));
}
#define CP_COMMIT() asm volatile("cp.async.commit_group;" ::: "memory")
#define CP_WAIT0()  asm volatile("cp.async.wait_group 0;" ::: "memory")
#define CP_WAIT1()  asm volatile("cp.async.wait_group 1;" ::: "memory")

// ---------------- preprocessing ----------------
__global__ void k_zero() {
    if (threadIdx.x < MAXT) g_cnt[threadIdx.x] = 0;
}
__global__ void k_count(const int* __restrict__ Z, int n) {
    __shared__ int sc[MAXT];
    if (threadIdx.x < MAXT) sc[threadIdx.x] = 0;
    __syncthreads();
    int i = blockIdx.x * blockDim.x + threadIdx.x;
    if (i < n) atomicAdd(&sc[Z[i]], 1);
    __syncthreads();
    if (threadIdx.x < MAXT) {
        int c = sc[threadIdx.x];
        if (c) atomicAdd(&g_cnt[threadIdx.x], c);
    }
}
__global__ void k_scan(int T) {
    if (threadIdx.x == 0 && blockIdx.x == 0) {
        int off = 0;
        for (int t = 0; t < T; t++) {
            g_off[t] = off;
            g_cur[t] = off;
            off += ((g_cnt[t] + TILE_M - 1) / TILE_M) * TILE_M;
        }
        for (int t = T; t <= MAXT; t++) g_off[t] = off;
    }
}
// block-aggregated scatter: one global atomic per type per block
__global__ void k_scatter(const int* __restrict__ Z, int n) {
    __shared__ int h[MAXT], base[MAXT], rk[MAXT];
    int tid = threadIdx.x;
    if (tid < MAXT) { h[tid] = 0; rk[tid] = 0; }
    __syncthreads();
    int i = blockIdx.x * blockDim.x + tid;
    int z = -1;
    if (i < n) { z = Z[i]; atomicAdd(&h[z], 1); }
    __syncthreads();
    if (tid < MAXT && h[tid]) base[tid] = atomicAdd(&g_cur[tid], h[tid]);
    __syncthreads();
    if (i < n) {
        int r = atomicAdd(&rk[z], 1);
        g_perm[base[z] + r] = i;
    }
}
// fill padded perm slots so GEMM tiles never read garbage rows
__global__ void k_pad(int T) {
    for (int t = 0; t < T; t++) {
        int s = g_off[t] + g_cnt[t], e = g_off[t + 1];
        if (g_cnt[t] <= 0) continue;
        int fill = g_perm[g_off[t]];
        for (int i = s + (int)threadIdx.x; i < e; i += blockDim.x) g_perm[i] = fill;
    }
}
// W0 fp32 -> fp16, same [t][k][h] layout
__global__ void k_w0h(const float* __restrict__ W0, int total8) {
    int i = blockIdx.x * blockDim.x + threadIdx.x;
    if (i < total8) {
        const float4* s = (const float4*)W0 + (size_t)i * 2;
        float4 v0 = s[0], v1 = s[1];
        __half2 h0 = __floats2half2_rn(v0.x, v0.y);
        __half2 h1 = __floats2half2_rn(v0.z, v0.w);
        __half2 h2 = __floats2half2_rn(v1.x, v1.y);
        __half2 h3 = __floats2half2_rn(v1.z, v1.w);
        uint4 o;
        o.x = *(uint32_t*)&h0; o.y = *(uint32_t*)&h1;
        o.z = *(uint32_t*)&h2; o.w = *(uint32_t*)&h3;
        *(uint4*)(g_w0h + (size_t)i * 8) = o;
    }
}

// ---------------- fused grouped HMMA GEMM + epilogue ----------------
__global__ __launch_bounds__(512, 1) void k_gemm(
    const float* __restrict__ q, const float* __restrict__ b0,
    const float* __restrict__ W1, const float* __restrict__ b1,
    float* __restrict__ out, int T) {

    extern __shared__ char sm[];
    const uint32_t sb = smem_u32(sm);
    int* sinfo = (int*)(sm + SP_INFO);
    int* sperm = (int*)(sm + SP_PERM);
    float* b0s = (float*)(sm + SP_B0S);
    float* w1s = (float*)(sm + SP_W1S);
    float* red = (float*)(sm + SP_RED);

    const int tid = threadIdx.x;
    const int wid = tid >> 5;
    const int lane = tid & 31;
    const int wm = wid & 3;    // 32-row block
    const int wn = wid >> 2;   // 64-col block
    const int g = lane >> 2;
    const int tig = lane & 3;
    const int tstart = blockIdx.x * TILE_M;

    if (tid == 0) {
        int t = 0;
        while (t < T && tstart >= g_off[t + 1]) t++;
        int nv = 0;
        if (t < T) nv = min(TILE_M, g_cnt[t] - (tstart - g_off[t]));
        sinfo[0] = t;
        sinfo[1] = nv;
    }
    __syncthreads();
    const int t = sinfo[0];
    const int nvalid = sinfo[1];
    if (nvalid <= 0) return;

    if (tid < TILE_M) sperm[tid] = g_perm[tstart + tid];
    if (tid < H1) {
        b0s[tid] = b0[t * H1 + tid];
        w1s[tid] = W1[t * H1 + tid];
    }
    __syncthreads();

    // ---- A: gather + fp32->fp16 into smem [128][LDA] ----
#pragma unroll
    for (int it = 0; it < 8; it++) {
        int idx = tid + it * 512;        // 4096 chunks of 8 halves
        int row = idx >> 5;
        int ch = idx & 31;
        int n = sperm[row];
        const float4* src = (const float4*)(q + (size_t)n * DQ + ch * 8);
        float4 v0 = src[0], v1 = src[1];
        __half2 h0 = __floats2half2_rn(v0.x, v0.y);
        __half2 h1 = __floats2half2_rn(v0.z, v0.w);
        __half2 h2 = __floats2half2_rn(v1.x, v1.y);
        __half2 h3 = __floats2half2_rn(v1.z, v1.w);
        uint4 o;
        o.x = *(uint32_t*)&h0; o.y = *(uint32_t*)&h1;
        o.z = *(uint32_t*)&h2; o.w = *(uint32_t*)&h3;
        *(uint4*)(sm + SP_A + (row * LDA + ch * 8) * 2) = o;
    }

    const __half* wbase = g_w0h + (size_t)t * DQ * H1;

    float s0 = 0.f, s1 = 0.f, s2 = 0.f, s3 = 0.f;

#pragma unroll
    for (int c = 0; c < 2; c++) {
        float acc[2][8][4];
#pragma unroll
        for (int mf = 0; mf < 2; mf++)
#pragma unroll
            for (int nf = 0; nf < 8; nf++)
#pragma unroll
                for (int e = 0; e < 4; e++) acc[mf][nf][e] = 0.f;

        // preload k-block 0
        {
#pragma unroll
            for (int it = 0; it < 2; it++) {
                int idx = tid + it * 512;
                int kk = idx >> 5, ch = idx & 31;
                cp16(sb + SP_B + (kk * LDB + ch * 8) * 2,
                     wbase + (size_t)kk * H1 + c * 256 + ch * 8);
            }
            CP_COMMIT();
        }
        int buf = 0;
        for (int kb = 0; kb < 8; kb++) {
            if (kb < 7) {
                int nb = buf ^ 1;
#pragma unroll
                for (int it = 0; it < 2; it++) {
                    int idx = tid + it * 512;
                    int kk = idx >> 5, ch = idx & 31;
                    cp16(sb + SP_B + nb * B_BUF_BYTES + (kk * LDB + ch * 8) * 2,
                         wbase + (size_t)((kb + 1) * 32 + kk) * H1 + c * 256 + ch * 8);
                }
                CP_COMMIT();
                CP_WAIT1();
            } else {
                CP_WAIT0();
            }
            __syncthreads();

            const uint32_t bbase = sb + SP_B + buf * B_BUF_BYTES;
#pragma unroll
            for (int kf = 0; kf < 2; kf++) {
                uint32_t a[2][4];
#pragma unroll
                for (int mf = 0; mf < 2; mf++) {
                    int row = wm * 32 + mf * 16 + (lane & 15);
                    int kc = kb * 32 + kf * 16 + (lane >> 4) * 8;
                    ldsm_x4(a[mf], sb + SP_A + (row * LDA + kc) * 2);
                }
#pragma unroll
                for (int nf16 = 0; nf16 < 4; nf16++) {
                    uint32_t b[4];
                    int kl = kf * 16 + ((lane >> 3) & 1) * 8 + (lane & 7);
                    int nn = wn * 64 + nf16 * 16 + (lane >> 4) * 8;
                    ldsm_x4_t(b, bbase + (kl * LDB + nn) * 2);
                    mma16816(acc[0][2 * nf16],     a[0], b[0], b[1]);
                    mma16816(acc[0][2 * nf16 + 1], a[0], b[2], b[3]);
                    mma16816(acc[1][2 * nf16],     a[1], b[0], b[1]);
                    mma16816(acc[1][2 * nf16 + 1], a[1], b[2], b[3]);
                }
            }
            __syncthreads();
            buf ^= 1;
        }

        // ---- epilogue for this chunk: tanh + dot(W1), per-thread partials ----
#pragma unroll
        for (int mf = 0; mf < 2; mf++) {
#pragma unroll
            for (int nf = 0; nf < 8; nf++) {
                int col = c * 256 + wn * 64 + nf * 8 + tig * 2;
                float v0 = tanhf(acc[mf][nf][0] + b0s[col])     * w1s[col];
                float v1 = tanhf(acc[mf][nf][1] + b0s[col + 1]) * w1s[col + 1];
                float v2 = tanhf(acc[mf][nf][2] + b0s[col])     * w1s[col];
                float v3 = tanhf(acc[mf][nf][3] + b0s[col + 1]) * w1s[col + 1];
                if (mf == 0) { s0 += v0 + v1; s1 += v2 + v3; }
                else         { s2 += v0 + v1; s3 += v2 + v3; }
            }
        }
    }

    // reduce over the 4-lane group (tig) — deterministic shuffle tree
    s0 += __shfl_xor_sync(0xffffffffu, s0, 1); s0 += __shfl_xor_sync(0xffffffffu, s0, 2);
    s1 += __shfl_xor_sync(0xffffffffu, s1, 1); s1 += __shfl_xor_sync(0xffffffffu, s1, 2);
    s2 += __shfl_xor_sync(0xffffffffu, s2, 1); s2 += __shfl_xor_sync(0xffffffffu, s2, 2);
    s3 += __shfl_xor_sync(0xffffffffu, s3, 1); s3 += __shfl_xor_sync(0xffffffffu, s3, 2);
    if (tig == 0) {
        int rbase = wn * 128 + wm * 32;
        red[rbase + g]      = s0;   // mf0, rows g
        red[rbase + 8 + g]  = s1;   // mf0, rows g+8
        red[rbase + 16 + g] = s2;   // mf1, rows g
        red[rbase + 24 + g] = s3;   // mf1, rows g+8
    }
    __syncthreads();
    if (tid < TILE_M && tid < nvalid) {
        float r = red[tid] + red[128 + tid] + red[256 + tid] + red[384 + tid];
        out[sperm[tid]] = r + __ldg(&b1[0]);
    }
}

extern "C" void kernel_launch(void* const* d_in, const int* in_sizes, int n_in,
                              void* d_out, int out_size) {
    const float* q  = (const float*)d_in[0];
    const int*   Z  = (const int*)d_in[1];
    const float* W0 = (const float*)d_in[2];
    const float* b0 = (const float*)d_in[3];
    const float* W1 = (const float*)d_in[4];
    const float* b1 = (const float*)d_in[5];
    float* out = (float*)d_out;

    const int N = in_sizes[1];
    int T = in_sizes[3] / H1;
    if (T < 1) T = 1;
    if (T > MAXT) T = MAXT;

    static int smem_set = 0;
    if (!smem_set) {
        cudaFuncSetAttribute(k_gemm, cudaFuncAttributeMaxDynamicSharedMemorySize, SM_DYN);
        smem_set = 1;
    }

    k_zero<<<1, 32>>>();
    k_count<<<(N + 255) / 256, 256>>>(Z, N);
    k_scan<<<1, 1>>>(T);
    k_scatter<<<(N + 255) / 256, 256>>>(Z, N);
    k_pad<<<1, 256>>>(T);
    int total8 = T * DQ * H1 / 8;
    k_w0h<<<(total8 + 255) / 256, 256>>>(W0, total8);

    const int tiles = (N + TILE_M - 1) / TILE_M + T;
    k_gemm<<<tiles, 512, SM_DYN>>>(q, b0, W1, b1, out, T);
}

// round 7
// speedup vs baseline: 5.6742x; 1.0235x over previous
#include <cuda_runtime.h>
#include <cuda_fp16.h>
#include <math.h>
#include <stdint.h>

#define DQ 256
#define H1 512
#define MAXT 8
#define NCAP 131072
#define TILE_M 128
#define LDA 264
#define LDB 264
#define KSTAGE 64
#define BSTAGE (KSTAGE * LDB * 2)       // 33792 bytes per B stage
#define SP_PERM 0
#define SP_B0S  544
#define SP_W1S  2592
#define SP_RED  4640
#define SP_A    6784                    // 128*LDA*2 = 67584
#define SP_B    74368
#define SM_DYN  (SP_B + 3 * BSTAGE)     // 175744

// ---------------- scratch ----------------
__device__ int g_cnt[MAXT];
__device__ int g_cur[MAXT];
__device__ int g_off[MAXT + 1];          // tile-count prefix (CTA mapping)
__device__ int g_perm[MAXT * NCAP];      // per-type capacity-N segments
__device__ __align__(16) __half g_w0h[MAXT * DQ * H1];

// ---------------- asm helpers (sm_103-safe, no 'a' features) ----------------
__device__ __forceinline__ uint32_t smem_u32(const void* p) {
    uint32_t a;
    asm("{ .reg .u64 t; cvta.to.shared.u64 t, %1; cvt.u32.u64 %0, t; }" : "=r"(a) : "l"(p));
    return a;
}
__device__ __forceinline__ void ldsm_x4(uint32_t* r, uint32_t addr) {
    asm volatile("ldmatrix.sync.aligned.m8n8.x4.shared.b16 {%0,%1,%2,%3}, [%4];"
                 : "=r"(r[0]), "=r"(r[1]), "=r"(r[2]), "=r"(r[3]) : "r"(addr));
}
__device__ __forceinline__ void ldsm_x4_t(uint32_t* r, uint32_t addr) {
    asm volatile("ldmatrix.sync.aligned.m8n8.x4.trans.shared.b16 {%0,%1,%2,%3}, [%4];"
                 : "=r"(r[0]), "=r"(r[1]), "=r"(r[2]), "=r"(r[3]) : "r"(addr));
}
__device__ __forceinline__ void mma16816(float* c, const uint32_t* a, uint32_t b0, uint32_t b1) {
    asm volatile(
        "mma.sync.aligned.m16n8k16.row.col.f32.f16.f16.f32 "
        "{%0,%1,%2,%3}, {%4,%5,%6,%7}, {%8,%9}, {%0,%1,%2,%3};"
        : "+f"(c[0]), "+f"(c[1]), "+f"(c[2]), "+f"(c[3])
        : "r"(a[0]), "r"(a[1]), "r"(a[2]), "r"(a[3]), "r"(b0), "r"(b1));
}
__device__ __forceinline__ void cp16(uint32_t dst, const void* src) {
    asm volatile("cp.async.cg.shared.global [%0], [%1], 16;" :: "r"(dst), "l"(src));
}
#define CP_COMMIT() asm volatile("cp.async.commit_group;" ::: "memory")
#define CP_WAIT0()  asm volatile("cp.async.wait_group 0;" ::: "memory")
#define CP_WAIT1()  asm volatile("cp.async.wait_group 1;" ::: "memory")

// accurate fast tanh: 2 MUFU + few ALU, abs err ~1e-7, overflow-safe
__device__ __forceinline__ float fast_tanh(float x) {
    float e = __expf(-2.0f * fabsf(x));
    float r = __fdividef(1.0f - e, 1.0f + e);
    return copysignf(r, x);
}

// ---------------- preprocessing ----------------
__global__ void k_zero(int n) {
    if (threadIdx.x < MAXT) g_cur[threadIdx.x] = threadIdx.x * n;
}
// single-pass scatter into per-type capacity-N segments
__global__ void k_scatter(const int* __restrict__ Z, int n) {
    __shared__ int h[MAXT], base[MAXT], rk[MAXT];
    int tid = threadIdx.x;
    if (tid < MAXT) { h[tid] = 0; rk[tid] = 0; }
    __syncthreads();
    int i = blockIdx.x * blockDim.x + tid;
    int z = -1;
    if (i < n) { z = Z[i]; atomicAdd(&h[z], 1); }
    __syncthreads();
    if (tid < MAXT && h[tid]) base[tid] = atomicAdd(&g_cur[tid], h[tid]);
    __syncthreads();
    if (i < n) {
        int r = atomicAdd(&rk[z], 1);
        g_perm[base[z] + r] = i;
    }
}
// counts + tile-offset prefix
__global__ void k_scan(int T, int n) {
    if (threadIdx.x == 0 && blockIdx.x == 0) {
        int off = 0;
        for (int t = 0; t < T; t++) {
            int c = g_cur[t] - t * n;
            g_cnt[t] = c;
            g_off[t] = off;
            off += (c + TILE_M - 1) / TILE_M;
        }
        for (int t = T; t <= MAXT; t++) g_off[t] = off;
    }
}
// W0 fp32 -> fp16 (same [t][k][h] layout)
__global__ void k_w0h(const float* __restrict__ W0, int total8) {
    int i = blockIdx.x * blockDim.x + threadIdx.x;
    if (i < total8) {
        const float4* s = (const float4*)W0 + (size_t)i * 2;
        float4 v0 = s[0], v1 = s[1];
        __half2 h0 = __floats2half2_rn(v0.x, v0.y);
        __half2 h1 = __floats2half2_rn(v0.z, v0.w);
        __half2 h2 = __floats2half2_rn(v1.x, v1.y);
        __half2 h3 = __floats2half2_rn(v1.z, v1.w);
        uint4 o;
        o.x = *(uint32_t*)&h0; o.y = *(uint32_t*)&h1;
        o.z = *(uint32_t*)&h2; o.w = *(uint32_t*)&h3;
        *(uint4*)(g_w0h + (size_t)i * 8) = o;
    }
}

// ---------------- fused grouped HMMA GEMM + epilogue ----------------
__global__ __launch_bounds__(512, 1) void k_gemm(
    const float* __restrict__ q, const float* __restrict__ b0,
    const float* __restrict__ W1, const float* __restrict__ b1,
    float* __restrict__ out, int T, int n) {

    extern __shared__ char sm[];
    const uint32_t sb = smem_u32(sm);
    int* sperm = (int*)(sm + SP_PERM);
    float* b0s = (float*)(sm + SP_B0S);
    float* w1s = (float*)(sm + SP_W1S);
    float* red = (float*)(sm + SP_RED);

    const int tid = threadIdx.x;
    const int lane = tid & 31;
    const int wid = tid >> 5;
    const int wm = wid & 3;
    const int wn = wid >> 2;
    const int g = lane >> 2;
    const int tig = lane & 3;

    // per-thread CTA->(type, tile) mapping (few cached LDGs, no barrier)
    const int b = blockIdx.x;
    int t = 0;
    while (t < T && b >= g_off[t + 1]) t++;
    if (t >= T) return;
    const int tile = b - g_off[t];
    const int nvalid = min(TILE_M, g_cnt[t] - tile * TILE_M);
    if (nvalid <= 0) return;
    const int pbase = t * n + tile * TILE_M;

    const __half* wbase = g_w0h + (size_t)t * DQ * H1;

    // prefetch B stages 0,1 immediately (overlaps everything below)
#pragma unroll
    for (int st = 0; st < 2; st++) {
#pragma unroll
        for (int it = 0; it < 4; it++) {
            int idx = tid + it * 512;
            int kk = idx >> 5, ch = idx & 31;
            cp16(sb + SP_B + st * BSTAGE + (kk * LDB + ch * 8) * 2,
                 wbase + (size_t)(st * KSTAGE + kk) * H1 + ch * 8);
        }
        CP_COMMIT();
    }

    if (tid < TILE_M) sperm[tid] = g_perm[pbase + min(tid, nvalid - 1)];
    if (tid < H1) {
        b0s[tid] = b0[t * H1 + tid];
        w1s[tid] = W1[t * H1 + tid];
    }
    __syncthreads();

    // A: gather + fp32->fp16 into smem [128][LDA]
#pragma unroll
    for (int it = 0; it < 8; it++) {
        int idx = tid + it * 512;
        int row = idx >> 5;
        int ch = idx & 31;
        int nr = sperm[row];
        const float4* src = (const float4*)(q + (size_t)nr * DQ + ch * 8);
        float4 v0 = src[0], v1 = src[1];
        __half2 h0 = __floats2half2_rn(v0.x, v0.y);
        __half2 h1 = __floats2half2_rn(v0.z, v0.w);
        __half2 h2 = __floats2half2_rn(v1.x, v1.y);
        __half2 h3 = __floats2half2_rn(v1.z, v1.w);
        uint4 o;
        o.x = *(uint32_t*)&h0; o.y = *(uint32_t*)&h1;
        o.z = *(uint32_t*)&h2; o.w = *(uint32_t*)&h3;
        *(uint4*)(sm + SP_A + (row * LDA + ch * 8) * 2) = o;
    }

    float acc[2][8][4];
#pragma unroll
    for (int mf = 0; mf < 2; mf++)
#pragma unroll
        for (int nf = 0; nf < 8; nf++)
#pragma unroll
            for (int e = 0; e < 4; e++) acc[mf][nf][e] = 0.f;

    float s0 = 0.f, s1 = 0.f, s2 = 0.f, s3 = 0.f;
    int bc = 0, bp = 2;   // compute / prefetch ring slots

    for (int s = 0; s < 8; s++) {
        // stage s -> chunk c = s>>2 (H1 half), k-block kb = s&3
        if (s < 7) { CP_WAIT1(); } else { CP_WAIT0(); }
        __syncthreads();

        if (s + 2 < 8) {
            int c2 = (s + 2) >> 2, kb2 = (s + 2) & 3;
            const __half* src0 = wbase + (size_t)(kb2 * KSTAGE) * H1 + c2 * 256;
            uint32_t dst = sb + SP_B + bp * BSTAGE;
#pragma unroll
            for (int it = 0; it < 4; it++) {
                int idx = tid + it * 512;
                int kk = idx >> 5, ch = idx & 31;
                cp16(dst + (kk * LDB + ch * 8) * 2, src0 + (size_t)kk * H1 + ch * 8);
            }
            CP_COMMIT();
        }

        const int kb = s & 3;
        const uint32_t bbase = sb + SP_B + bc * BSTAGE;
#pragma unroll
        for (int kf = 0; kf < 4; kf++) {
            uint32_t a[2][4];
#pragma unroll
            for (int mf = 0; mf < 2; mf++) {
                int row = wm * 32 + mf * 16 + (lane & 15);
                int kc = kb * KSTAGE + kf * 16 + (lane >> 4) * 8;
                ldsm_x4(a[mf], sb + SP_A + (row * LDA + kc) * 2);
            }
#pragma unroll
            for (int nf16 = 0; nf16 < 4; nf16++) {
                uint32_t bf[4];
                int kl = kf * 16 + ((lane >> 3) & 1) * 8 + (lane & 7);
                int nn = wn * 64 + nf16 * 16 + (lane >> 4) * 8;
                ldsm_x4_t(bf, bbase + (kl * LDB + nn) * 2);
                mma16816(acc[0][2 * nf16],     a[0], bf[0], bf[1]);
                mma16816(acc[0][2 * nf16 + 1], a[0], bf[2], bf[3]);
                mma16816(acc[1][2 * nf16],     a[1], bf[0], bf[1]);
                mma16816(acc[1][2 * nf16 + 1], a[1], bf[2], bf[3]);
            }
        }

        if (kb == 3) {   // chunk finished: tanh + dot(W1) epilogue, reset acc
            const int c = s >> 2;
#pragma unroll
            for (int mf = 0; mf < 2; mf++) {
#pragma unroll
                for (int nf = 0; nf < 8; nf++) {
                    int col = c * 256 + wn * 64 + nf * 8 + tig * 2;
                    float v0 = fast_tanh(acc[mf][nf][0] + b0s[col])     * w1s[col];
                    float v1 = fast_tanh(acc[mf][nf][1] + b0s[col + 1]) * w1s[col + 1];
                    float v2 = fast_tanh(acc[mf][nf][2] + b0s[col])     * w1s[col];
                    float v3 = fast_tanh(acc[mf][nf][3] + b0s[col + 1]) * w1s[col + 1];
                    if (mf == 0) { s0 += v0 + v1; s1 += v2 + v3; }
                    else         { s2 += v0 + v1; s3 += v2 + v3; }
                    acc[mf][nf][0] = 0.f; acc[mf][nf][1] = 0.f;
                    acc[mf][nf][2] = 0.f; acc[mf][nf][3] = 0.f;
                }
            }
        }

        bc = (bc == 2) ? 0 : bc + 1;
        bp = (bp == 2) ? 0 : bp + 1;
    }

    // deterministic reduction: shuffle over 4-lane group, then 4-slice smem sum
    s0 += __shfl_xor_sync(0xffffffffu, s0, 1); s0 += __shfl_xor_sync(0xffffffffu, s0, 2);
    s1 += __shfl_xor_sync(0xffffffffu, s1, 1); s1 += __shfl_xor_sync(0xffffffffu, s1, 2);
    s2 += __shfl_xor_sync(0xffffffffu, s2, 1); s2 += __shfl_xor_sync(0xffffffffu, s2, 2);
    s3 += __shfl_xor_sync(0xffffffffu, s3, 1); s3 += __shfl_xor_sync(0xffffffffu, s3, 2);
    if (tig == 0) {
        int rbase = wn * 128 + wm * 32;
        red[rbase + g]      = s0;
        red[rbase + 8 + g]  = s1;
        red[rbase + 16 + g] = s2;
        red[rbase + 24 + g] = s3;
    }
    __syncthreads();
    if (tid < TILE_M && tid < nvalid) {
        float r = red[tid] + red[128 + tid] + red[256 + tid] + red[384 + tid];
        out[sperm[tid]] = r + __ldg(&b1[0]);
    }
}

extern "C" void kernel_launch(void* const* d_in, const int* in_sizes, int n_in,
                              void* d_out, int out_size) {
    const float* q  = (const float*)d_in[0];
    const int*   Z  = (const int*)d_in[1];
    const float* W0 = (const float*)d_in[2];
    const float* b0 = (const float*)d_in[3];
    const float* W1 = (const float*)d_in[4];
    const float* b1 = (const float*)d_in[5];
    float* out = (float*)d_out;

    const int N = in_sizes[1];
    int T = in_sizes[3] / H1;
    if (T < 1) T = 1;
    if (T > MAXT) T = MAXT;

    static int smem_set = 0;
    if (!smem_set) {
        cudaFuncSetAttribute(k_gemm, cudaFuncAttributeMaxDynamicSharedMemorySize, SM_DYN);
        smem_set = 1;
    }

    k_zero<<<1, 32>>>(N);
    k_scatter<<<(N + 511) / 512, 512>>>(Z, N);
    k_scan<<<1, 1>>>(T, N);
    int total8 = T * DQ * H1 / 8;
    k_w0h<<<(total8 + 255) / 256, 256>>>(W0, total8);

    const int tiles = (N + TILE_M - 1) / TILE_M + T;
    k_gemm<<<tiles, 512, SM_DYN>>>(q, b0, W1, b1, out, T, N);
}